// round 1
// baseline (speedup 1.0000x reference)
#include <cuda_runtime.h>
#include <math.h>

#define BB 32
#define CC 256
#define NN 3136
#define OUTC 32896            // 256*257/2
#define MATSZ (BB*CC*CC)

// ---------------- scratch (static device globals; no allocation) ----------------
__device__ float g_A[MATSZ];   // sigma, then A = sigma/trace
__device__ float g_B0[MATSZ];
__device__ float g_B1[MATSZ];
__device__ float g_Y0[MATSZ];
__device__ float g_Y1[MATSZ];
__device__ float g_Z0[MATSZ];
__device__ float g_Z1[MATSZ];
__device__ float g_T[MATSZ];
__device__ float g_tr[BB];
__device__ float g_s[BB*CC];

// ---------------- row sums: s[b][c] = sum_n x[b][c][n] ----------------
__global__ __launch_bounds__(256) void rowsum_kernel(const float* __restrict__ X,
                                                     float* __restrict__ s) {
    int c = blockIdx.x, b = blockIdx.y;
    const float* row = X + ((size_t)b * CC + c) * NN;
    float acc = 0.f;
    for (int k = threadIdx.x; k < NN; k += 256) acc += row[k];
    __shared__ float sm[256];
    sm[threadIdx.x] = acc;
    __syncthreads();
    for (int st = 128; st > 0; st >>= 1) {
        if (threadIdx.x < st) sm[threadIdx.x] += sm[threadIdx.x + st];
        __syncthreads();
    }
    if (threadIdx.x == 0) s[b * CC + c] = sm[0];
}

// ---------------- gram/cov: Sig[b] = X Xt / n - s s^T / n^2 ----------------
// 64x64 tile, 256 threads (16x16), 4x4 micro-tile, K chunks of 32
__global__ __launch_bounds__(256) void gram_kernel(const float* __restrict__ X,
                                                   const float* __restrict__ s,
                                                   float* __restrict__ Sig) {
    int b = blockIdx.z;
    const float* Xb = X + (size_t)b * CC * NN;
    __shared__ float Si[32][65];
    __shared__ float Sj[32][65];
    int tid = threadIdx.x;
    int tx = tid & 15, ty = tid >> 4;
    int i0 = blockIdx.x * 64, j0 = blockIdx.y * 64;
    float acc[4][4] = {};

    int lrow = tid >> 5;       // 0..7
    int lkk  = tid & 31;       // 0..31
    for (int k0 = 0; k0 < NN; k0 += 32) {
#pragma unroll
        for (int r = 0; r < 8; ++r) {
            int row = lrow + r * 8;
            Si[lkk][row] = Xb[(size_t)(i0 + row) * NN + k0 + lkk];
            Sj[lkk][row] = Xb[(size_t)(j0 + row) * NN + k0 + lkk];
        }
        __syncthreads();
#pragma unroll
        for (int kk = 0; kk < 32; ++kk) {
            float a[4], bv[4];
#pragma unroll
            for (int i = 0; i < 4; ++i) a[i] = Si[kk][ty * 4 + i];
#pragma unroll
            for (int j = 0; j < 4; ++j) bv[j] = Sj[kk][tx * 4 + j];
#pragma unroll
            for (int i = 0; i < 4; ++i)
#pragma unroll
                for (int j = 0; j < 4; ++j) acc[i][j] += a[i] * bv[j];
        }
        __syncthreads();
    }

    const float inv_n = 1.0f / (float)NN;
    const float inv_n2 = inv_n * inv_n;
#pragma unroll
    for (int i = 0; i < 4; ++i) {
        int gi = i0 + ty * 4 + i;
        float si = s[b * CC + gi];
#pragma unroll
        for (int j = 0; j < 4; ++j) {
            int gj = j0 + tx * 4 + j;
            Sig[(size_t)b * CC * CC + (size_t)gi * CC + gj] =
                acc[i][j] * inv_n - si * s[b * CC + gj] * inv_n2;
        }
    }
}

// ---------------- trace ----------------
__global__ __launch_bounds__(256) void trace_kernel(const float* __restrict__ A,
                                                    float* __restrict__ tr) {
    int b = blockIdx.x, c = threadIdx.x;
    __shared__ float sm[256];
    sm[c] = A[(size_t)b * CC * CC + (size_t)c * CC + c];
    __syncthreads();
    for (int st = 128; st > 0; st >>= 1) {
        if (c < st) sm[c] += sm[c + st];
        __syncthreads();
    }
    if (c == 0) tr[b] = sm[0];
}

// ---------------- ew_init: A /= tr (in place); B0 = 1.5 I - 0.5 A ----------------
__global__ __launch_bounds__(256) void ew_init_kernel(float* __restrict__ A,
                                                      const float* __restrict__ tr,
                                                      float* __restrict__ B0) {
    int i = blockIdx.x, b = blockIdx.y, j = threadIdx.x;
    size_t idx = (size_t)b * CC * CC + (size_t)i * CC + j;
    float invt = 1.0f / tr[b];
    float a = A[idx] * invt;
    A[idx] = a;
    B0[idx] = (i == j ? 1.5f : 0.0f) - 0.5f * a;
}

// ---------------- ew_b: Bn = 1.5 I - 0.5 T ----------------
__global__ __launch_bounds__(256) void ew_b_kernel(const float* __restrict__ T,
                                                   float* __restrict__ Bn) {
    int i = blockIdx.x, b = blockIdx.y, j = threadIdx.x;
    size_t idx = (size_t)b * CC * CC + (size_t)i * CC + j;
    Bn[idx] = (i == j ? 1.5f : 0.0f) - 0.5f * T[idx];
}

// ---------------- batched GEMM 256x256x256: Cm[b] = A[b] @ Bm[b] ----------------
__global__ __launch_bounds__(256) void gemm256_kernel(const float* __restrict__ A,
                                                      const float* __restrict__ Bm,
                                                      float* __restrict__ Cm) {
    int b = blockIdx.z;
    const float* Ab = A + (size_t)b * CC * CC;
    const float* Bb = Bm + (size_t)b * CC * CC;
    float* Cb = Cm + (size_t)b * CC * CC;
    __shared__ float As[32][65];
    __shared__ float Bs[32][65];
    int tid = threadIdx.x;
    int tx = tid & 15, ty = tid >> 4;
    int i0 = blockIdx.x * 64, j0 = blockIdx.y * 64;
    float acc[4][4] = {};

    int lrowA = tid >> 5;   // 0..7
    int lkkA  = tid & 31;   // 0..31
    int ljjB  = tid & 63;   // 0..63
    int lkkB  = tid >> 6;   // 0..3

    for (int k0 = 0; k0 < CC; k0 += 32) {
#pragma unroll
        for (int r = 0; r < 8; ++r) {
            int row = lrowA + r * 8;
            As[lkkA][row] = Ab[(size_t)(i0 + row) * CC + k0 + lkkA];
            Bs[lkkB + r * 4][ljjB] = Bb[(size_t)(k0 + lkkB + r * 4) * CC + j0 + ljjB];
        }
        __syncthreads();
#pragma unroll
        for (int kk = 0; kk < 32; ++kk) {
            float a[4], bv[4];
#pragma unroll
            for (int i = 0; i < 4; ++i) a[i] = As[kk][ty * 4 + i];
#pragma unroll
            for (int j = 0; j < 4; ++j) bv[j] = Bs[kk][tx * 4 + j];
#pragma unroll
            for (int i = 0; i < 4; ++i)
#pragma unroll
                for (int j = 0; j < 4; ++j) acc[i][j] += a[i] * bv[j];
        }
        __syncthreads();
    }

#pragma unroll
    for (int i = 0; i < 4; ++i) {
        int gi = i0 + ty * 4 + i;
#pragma unroll
        for (int j = 0; j < 4; ++j) {
            Cb[(size_t)gi * CC + j0 + tx * 4 + j] = acc[i][j];
        }
    }
}

// ---------------- triuvec: out[b][base(r)+c-r] = Y[b][r][c] * sqrt(tr[b]) ----------------
__global__ __launch_bounds__(256) void triuvec_kernel(const float* __restrict__ Y,
                                                      const float* __restrict__ tr,
                                                      float* __restrict__ out) {
    int r = blockIdx.x, b = blockIdx.y;
    float sc = sqrtf(tr[b]);
    int base = r * CC - (r * (r - 1)) / 2;
    const float* Yrow = Y + (size_t)b * CC * CC + (size_t)r * CC;
    float* ob = out + (size_t)b * OUTC + base - r;
    for (int c = r + threadIdx.x; c < CC; c += 256) {
        ob[c] = Yrow[c] * sc;
    }
}

// ---------------- launch ----------------
extern "C" void kernel_launch(void* const* d_in, const int* in_sizes, int n_in,
                              void* d_out, int out_size) {
    const float* x = (const float*)d_in[0];
    float* out = (float*)d_out;

    float *A, *B0, *B1, *Y0, *Y1, *Z0, *Z1, *T, *tr, *s;
    cudaGetSymbolAddress((void**)&A, g_A);
    cudaGetSymbolAddress((void**)&B0, g_B0);
    cudaGetSymbolAddress((void**)&B1, g_B1);
    cudaGetSymbolAddress((void**)&Y0, g_Y0);
    cudaGetSymbolAddress((void**)&Y1, g_Y1);
    cudaGetSymbolAddress((void**)&Z0, g_Z0);
    cudaGetSymbolAddress((void**)&Z1, g_Z1);
    cudaGetSymbolAddress((void**)&T, g_T);
    cudaGetSymbolAddress((void**)&tr, g_tr);
    cudaGetSymbolAddress((void**)&s, g_s);

    // 1) row sums
    rowsum_kernel<<<dim3(CC, BB), 256>>>(x, s);
    // 2) covariance into A
    gram_kernel<<<dim3(4, 4, BB), 256>>>(x, s, A);
    // 3) trace
    trace_kernel<<<BB, 256>>>(A, tr);
    // 4) A /= trace ; B0 = 1.5I - 0.5A
    ew_init_kernel<<<dim3(CC, BB), 256>>>(A, tr, B0);
    // 5) Y = A @ B0 ; Z = B0 (by pointer)
    dim3 ggrid(4, 4, BB);
    gemm256_kernel<<<ggrid, 256>>>(A, B0, Y0);

    float* Yc = Y0;
    float* Zc = B0;
    for (int it = 0; it < 4; ++it) {
        float* Bn = (it & 1) ? B0 : B1;      // iter0 must avoid B0 (== Zc)
        float* Yn = (Yc == Y0) ? Y1 : Y0;
        float* Zn = (it & 1) ? Z1 : Z0;
        gemm256_kernel<<<ggrid, 256>>>(Zc, Yc, T);   // T = Z @ Y
        ew_b_kernel<<<dim3(CC, BB), 256>>>(T, Bn);   // Bn = 1.5I - 0.5T
        gemm256_kernel<<<ggrid, 256>>>(Yc, Bn, Yn);  // Ynew = Y @ Bn
        gemm256_kernel<<<ggrid, 256>>>(Bn, Zc, Zn);  // Znew = Bn @ Z
        Yc = Yn;
        Zc = Zn;
    }

    // 6) scale by sqrt(trace) + upper-triangle extraction
    triuvec_kernel<<<dim3(CC, BB), 256>>>(Yc, tr, out);
}

// round 2
// speedup vs baseline: 1.5389x; 1.5389x over previous
#include <cuda_runtime.h>
#include <math.h>

#define BB 32
#define CC 256
#define NN 3136
#define OUTC 32896            // 256*257/2
#define MATSZ (BB*CC*CC)
#define LP 132                // smem row pitch (words), 132 % 32 == 4 -> conflict-free frags

// ---------------- scratch ----------------
__device__ float g_A[MATSZ];
__device__ float g_B0[MATSZ];
__device__ float g_B1[MATSZ];
__device__ float g_Y0[MATSZ];
__device__ float g_Y1[MATSZ];
__device__ float g_Z0[MATSZ];
__device__ float g_Z1[MATSZ];
__device__ float g_s[BB*CC];
__device__ float g_q[BB*CC];
__device__ float g_tr[BB];

// ---------------- helpers ----------------
__device__ __forceinline__ unsigned f2tf(float f) {
    unsigned r;
    asm("cvt.rna.tf32.f32 %0, %1;" : "=r"(r) : "f"(f));
    return r;
}

__device__ __forceinline__ void mma8(float* c, const unsigned* a, const unsigned* b) {
    asm volatile(
        "mma.sync.aligned.m16n8k8.row.col.f32.tf32.tf32.f32 "
        "{%0,%1,%2,%3}, {%4,%5,%6,%7}, {%8,%9}, {%0,%1,%2,%3};"
        : "+f"(c[0]), "+f"(c[1]), "+f"(c[2]), "+f"(c[3])
        : "r"(a[0]), "r"(a[1]), "r"(a[2]), "r"(a[3]), "r"(b[0]), "r"(b[1]));
}

struct F8 { float4 a, b; };
__device__ __forceinline__ F8 ld8(const float* p) {
    F8 r;
    r.a = *(const float4*)p;
    r.b = *(const float4*)(p + 4);
    return r;
}

// transpose store: smem[k][row] layout, thread r=tid>>1 covers rows, koff=(tid&1)*8
__device__ __forceinline__ void st_trans(F8 v, unsigned* sh, unsigned* sl, int tid) {
    int r = tid >> 1, koff = (tid & 1) * 8;
    float vv[8] = {v.a.x, v.a.y, v.a.z, v.a.w, v.b.x, v.b.y, v.b.z, v.b.w};
#pragma unroll
    for (int e = 0; e < 8; ++e) {
        unsigned hi = f2tf(vv[e]);
        sh[(koff + e) * LP + r] = hi;
        sl[(koff + e) * LP + r] = f2tf(vv[e] - __uint_as_float(hi));
    }
}

// direct store: smem[k][col], thread rB=tid>>4 row, j=(tid&15)*8 cols
__device__ __forceinline__ void st_direct(F8 v, unsigned* sh, unsigned* sl, int tid) {
    int rB = tid >> 4, j = (tid & 15) * 8;
    float vv[8] = {v.a.x, v.a.y, v.a.z, v.a.w, v.b.x, v.b.y, v.b.z, v.b.w};
    unsigned h[8], l[8];
#pragma unroll
    for (int e = 0; e < 8; ++e) {
        h[e] = f2tf(vv[e]);
        l[e] = f2tf(vv[e] - __uint_as_float(h[e]));
    }
    uint4* ph = (uint4*)&sh[rB * LP + j];
    uint4* pl = (uint4*)&sl[rB * LP + j];
    ph[0] = make_uint4(h[0], h[1], h[2], h[3]);
    ph[1] = make_uint4(h[4], h[5], h[6], h[7]);
    pl[0] = make_uint4(l[0], l[1], l[2], l[3]);
    pl[1] = make_uint4(l[4], l[5], l[6], l[7]);
}

// 16-deep K chunk: 2 k-steps of 8, 4x4 mma tiles per warp, tf32x3 split
__device__ __forceinline__ void compute_chunk(const unsigned* sAh, const unsigned* sAl,
                                              const unsigned* sBh, const unsigned* sBl,
                                              float acc[4][4][4], int wm, int wn, int g, int t) {
#pragma unroll
    for (int ks = 0; ks < 16; ks += 8) {
        unsigned ah[4][4], al[4][4], bh[4][2], bl[4][2];
        int kt = ks + t;
#pragma unroll
        for (int it = 0; it < 4; ++it) {
            int m0 = wm * 64 + it * 16 + g;
            ah[it][0] = sAh[kt * LP + m0];
            ah[it][1] = sAh[kt * LP + m0 + 8];
            ah[it][2] = sAh[(kt + 4) * LP + m0];
            ah[it][3] = sAh[(kt + 4) * LP + m0 + 8];
            al[it][0] = sAl[kt * LP + m0];
            al[it][1] = sAl[kt * LP + m0 + 8];
            al[it][2] = sAl[(kt + 4) * LP + m0];
            al[it][3] = sAl[(kt + 4) * LP + m0 + 8];
        }
#pragma unroll
        for (int jt = 0; jt < 4; ++jt) {
            int n0 = wn * 32 + jt * 8 + g;
            bh[jt][0] = sBh[kt * LP + n0];
            bh[jt][1] = sBh[(kt + 4) * LP + n0];
            bl[jt][0] = sBl[kt * LP + n0];
            bl[jt][1] = sBl[(kt + 4) * LP + n0];
        }
#pragma unroll
        for (int it = 0; it < 4; ++it)
#pragma unroll
            for (int jt = 0; jt < 4; ++jt) {
                mma8(acc[it][jt], ah[it], bh[jt]);
                mma8(acc[it][jt], ah[it], bl[jt]);
                mma8(acc[it][jt], al[it], bh[jt]);
            }
    }
}

// ---------------- row sums + sumsq ----------------
__global__ __launch_bounds__(256) void rowsumq_kernel(const float* __restrict__ X,
                                                      float* __restrict__ s,
                                                      float* __restrict__ q) {
    int c = blockIdx.x, b = blockIdx.y;
    const float4* row = (const float4*)(X + ((size_t)b * CC + c) * NN);
    float acc = 0.f, accq = 0.f;
    for (int i = threadIdx.x; i < NN / 4; i += 256) {
        float4 v = row[i];
        acc += v.x + v.y + v.z + v.w;
        accq += v.x * v.x + v.y * v.y + v.z * v.z + v.w * v.w;
    }
    __shared__ float ss[256], sq[256];
    ss[threadIdx.x] = acc;
    sq[threadIdx.x] = accq;
    __syncthreads();
    for (int st = 128; st > 0; st >>= 1) {
        if (threadIdx.x < st) {
            ss[threadIdx.x] += ss[threadIdx.x + st];
            sq[threadIdx.x] += sq[threadIdx.x + st];
        }
        __syncthreads();
    }
    if (threadIdx.x == 0) {
        s[b * CC + c] = ss[0];
        q[b * CC + c] = sq[0];
    }
}

// ---------------- trace: tr = sum_c (q_c/n - s_c^2/n^2) ----------------
__global__ __launch_bounds__(256) void trred_kernel(const float* __restrict__ s,
                                                    const float* __restrict__ q,
                                                    float* __restrict__ tr) {
    int b = blockIdx.x, c = threadIdx.x;
    const float inv_n = 1.0f / (float)NN;
    const float inv_n2 = inv_n * inv_n;
    float sv = s[b * CC + c];
    float v = q[b * CC + c] * inv_n - sv * sv * inv_n2;
    __shared__ float sm[256];
    sm[c] = v;
    __syncthreads();
    for (int st = 128; st > 0; st >>= 1) {
        if (c < st) sm[c] += sm[c + st];
        __syncthreads();
    }
    if (c == 0) tr[b] = sm[0];
}

// ---------------- gram: A = (XX^T/n - ss^T/n^2)/tr ; B0 = 1.5I - 0.5A ----------------
// grid (3,1,32): tiles (0,0),(0,1),(1,1) of 128x128; tile 1 mirror-stores lower block.
__global__ __launch_bounds__(256, 1) void gram_mma_kernel(const float* __restrict__ X,
                                                          const float* __restrict__ s,
                                                          const float* __restrict__ trv,
                                                          float* __restrict__ Ao,
                                                          float* __restrict__ B0o) {
    __shared__ unsigned sAh[16 * LP], sAl[16 * LP], sBh[16 * LP], sBl[16 * LP];
    int b = blockIdx.z;
    int tile = blockIdx.x;
    int i0 = (tile == 2) ? 128 : 0;
    int j0 = (tile != 0) ? 128 : 0;
    bool mirror = (tile == 1);
    const float* Xb = X + (size_t)b * CC * NN;
    int tid = threadIdx.x;
    int warp = tid >> 5, lane = tid & 31;
    int wm = warp >> 2, wn = warp & 3, g = lane >> 2, t = lane & 3;
    float acc[4][4][4] = {};

    int rA = tid >> 1, koff = (tid & 1) * 8;
    const float* pA = Xb + (size_t)(i0 + rA) * NN + koff;
    const float* pB = Xb + (size_t)(j0 + rA) * NN + koff;
    F8 va = ld8(pA), vb = ld8(pB);
    for (int k0 = 0; k0 < NN; k0 += 16) {
        __syncthreads();
        st_trans(va, sAh, sAl, tid);
        st_trans(vb, sBh, sBl, tid);
        __syncthreads();
        if (k0 + 16 < NN) {
            va = ld8(pA + k0 + 16);
            vb = ld8(pB + k0 + 16);
        }
        compute_chunk(sAh, sAl, sBh, sBl, acc, wm, wn, g, t);
    }

    const float inv_n = 1.0f / (float)NN;
    const float inv_n2 = inv_n * inv_n;
    float invtr = 1.0f / trv[b];
    float* Ab = Ao + (size_t)b * CC * CC;
    float* Bb = B0o + (size_t)b * CC * CC;
#pragma unroll
    for (int it = 0; it < 4; ++it)
#pragma unroll
        for (int jt = 0; jt < 4; ++jt) {
            int gi = i0 + wm * 64 + it * 16 + g;
            int gj = j0 + wn * 32 + jt * 8 + 2 * t;
            float* ca = acc[it][jt];
#pragma unroll
            for (int h = 0; h < 2; ++h) {
                int r = gi + h * 8;
                float si = s[b * CC + r];
                float sj0 = s[b * CC + gj], sj1 = s[b * CC + gj + 1];
                float a0 = (ca[h * 2 + 0] * inv_n - si * sj0 * inv_n2) * invtr;
                float a1 = (ca[h * 2 + 1] * inv_n - si * sj1 * inv_n2) * invtr;
                float w0 = (r == gj ? 1.5f : 0.0f) - 0.5f * a0;
                float w1 = (r == gj + 1 ? 1.5f : 0.0f) - 0.5f * a1;
                *(float2*)&Ab[(size_t)r * CC + gj] = make_float2(a0, a1);
                *(float2*)&Bb[(size_t)r * CC + gj] = make_float2(w0, w1);
                if (mirror) {
                    Ab[(size_t)gj * CC + r] = a0;
                    Ab[(size_t)(gj + 1) * CC + r] = a1;
                    Bb[(size_t)gj * CC + r] = w0;
                    Bb[(size_t)(gj + 1) * CC + r] = w1;
                }
            }
        }
}

// ---------------- NS batched GEMM, 256^3, fused epilogues ----------------
// EPI 0: C = A@B          EPI 1: C = 1.5I - 0.5(A@B)      EPI 2: triu(A@B * sqrt(tr)) -> out
template <int EPI>
__global__ __launch_bounds__(256, 1) void ns_gemm_kernel(const float* __restrict__ Ag,
                                                         const float* __restrict__ Bg,
                                                         float* __restrict__ Cg,
                                                         const float* __restrict__ trv,
                                                         float* __restrict__ outg) {
    __shared__ unsigned sAh[16 * LP], sAl[16 * LP], sBh[16 * LP], sBl[16 * LP];
    int b = blockIdx.z;
    int tile = blockIdx.x;
    int i0 = (tile == 2) ? 128 : 0;
    int j0 = (tile != 0) ? 128 : 0;
    bool mirror = (tile == 1);
    const float* Ab = Ag + (size_t)b * CC * CC;
    const float* Bb = Bg + (size_t)b * CC * CC;
    int tid = threadIdx.x;
    int warp = tid >> 5, lane = tid & 31;
    int wm = warp >> 2, wn = warp & 3, g = lane >> 2, t = lane & 3;
    float acc[4][4][4] = {};

    int rA = tid >> 1, koff = (tid & 1) * 8;
    int rB = tid >> 4, jB = (tid & 15) * 8;
    const float* pA = Ab + (size_t)(i0 + rA) * CC + koff;
    const float* pB = Bb + (size_t)rB * CC + j0 + jB;
    F8 va = ld8(pA), vb = ld8(pB);
    for (int k0 = 0; k0 < CC; k0 += 16) {
        __syncthreads();
        st_trans(va, sAh, sAl, tid);
        st_direct(vb, sBh, sBl, tid);
        __syncthreads();
        if (k0 + 16 < CC) {
            va = ld8(pA + k0 + 16);
            vb = ld8(pB + (size_t)(k0 + 16) * CC);
        }
        compute_chunk(sAh, sAl, sBh, sBl, acc, wm, wn, g, t);
    }

    float scale = 0.f;
    if (EPI == 2) scale = sqrtf(trv[b]);
    float* Cb = (EPI == 2) ? nullptr : (Cg + (size_t)b * CC * CC);
#pragma unroll
    for (int it = 0; it < 4; ++it)
#pragma unroll
        for (int jt = 0; jt < 4; ++jt) {
            int gi = i0 + wm * 64 + it * 16 + g;
            int gj = j0 + wn * 32 + jt * 8 + 2 * t;
            float* ca = acc[it][jt];
#pragma unroll
            for (int h = 0; h < 2; ++h) {
                int r = gi + h * 8;
                float v0 = ca[h * 2 + 0], v1 = ca[h * 2 + 1];
                if (EPI == 0) {
                    *(float2*)&Cb[(size_t)r * CC + gj] = make_float2(v0, v1);
                    if (mirror) {
                        Cb[(size_t)gj * CC + r] = v0;
                        Cb[(size_t)(gj + 1) * CC + r] = v1;
                    }
                } else if (EPI == 1) {
                    float w0 = (r == gj ? 1.5f : 0.0f) - 0.5f * v0;
                    float w1 = (r == gj + 1 ? 1.5f : 0.0f) - 0.5f * v1;
                    *(float2*)&Cb[(size_t)r * CC + gj] = make_float2(w0, w1);
                    if (mirror) {
                        Cb[(size_t)gj * CC + r] = w0;
                        Cb[(size_t)(gj + 1) * CC + r] = w1;
                    }
                } else {
                    int base = r * CC - (r * (r - 1)) / 2 - r;
                    if (gj >= r) {
                        outg[(size_t)b * OUTC + base + gj] = v0 * scale;
                        outg[(size_t)b * OUTC + base + gj + 1] = v1 * scale;
                    } else if (gj + 1 == r) {
                        outg[(size_t)b * OUTC + base + gj + 1] = v1 * scale;
                    }
                }
            }
        }
}

// ---------------- launch ----------------
extern "C" void kernel_launch(void* const* d_in, const int* in_sizes, int n_in,
                              void* d_out, int out_size) {
    const float* x = (const float*)d_in[0];
    float* out = (float*)d_out;

    float *A, *B0, *B1, *Y0, *Y1, *Z0, *Z1, *s, *q, *tr;
    cudaGetSymbolAddress((void**)&A, g_A);
    cudaGetSymbolAddress((void**)&B0, g_B0);
    cudaGetSymbolAddress((void**)&B1, g_B1);
    cudaGetSymbolAddress((void**)&Y0, g_Y0);
    cudaGetSymbolAddress((void**)&Y1, g_Y1);
    cudaGetSymbolAddress((void**)&Z0, g_Z0);
    cudaGetSymbolAddress((void**)&Z1, g_Z1);
    cudaGetSymbolAddress((void**)&s, g_s);
    cudaGetSymbolAddress((void**)&q, g_q);
    cudaGetSymbolAddress((void**)&tr, g_tr);

    rowsumq_kernel<<<dim3(CC, BB), 256>>>(x, s, q);
    trred_kernel<<<BB, 256>>>(s, q, tr);

    dim3 gg(3, 1, BB);
    gram_mma_kernel<<<gg, 256>>>(x, s, tr, A, B0);

    // Y0 = A @ B0 ; Z = B0
    ns_gemm_kernel<0><<<gg, 256>>>(A, B0, Y0, nullptr, nullptr);
    // iter 1
    ns_gemm_kernel<1><<<gg, 256>>>(B0, Y0, B1, nullptr, nullptr);  // B1 = 1.5I-0.5(B0@Y0)
    ns_gemm_kernel<0><<<gg, 256>>>(Y0, B1, Y1, nullptr, nullptr);
    ns_gemm_kernel<0><<<gg, 256>>>(B1, B0, Z0, nullptr, nullptr);
    // iter 2
    ns_gemm_kernel<1><<<gg, 256>>>(Z0, Y1, B0, nullptr, nullptr);
    ns_gemm_kernel<0><<<gg, 256>>>(Y1, B0, Y0, nullptr, nullptr);
    ns_gemm_kernel<0><<<gg, 256>>>(B0, Z0, Z1, nullptr, nullptr);
    // iter 3
    ns_gemm_kernel<1><<<gg, 256>>>(Z1, Y0, B1, nullptr, nullptr);
    ns_gemm_kernel<0><<<gg, 256>>>(Y0, B1, Y1, nullptr, nullptr);
    ns_gemm_kernel<0><<<gg, 256>>>(B1, Z1, Z0, nullptr, nullptr);
    // iter 4 (Z update dead -> dropped)
    ns_gemm_kernel<1><<<gg, 256>>>(Z0, Y1, B0, nullptr, nullptr);
    ns_gemm_kernel<2><<<gg, 256>>>(Y1, B0, nullptr, tr, out);  // triu(Y@B0)*sqrt(tr)
}

// round 4
// speedup vs baseline: 1.6517x; 1.0733x over previous
#include <cuda_runtime.h>
#include <math.h>

#define BB 32
#define CC 256
#define NN 3136
#define OUTC 32896            // 256*257/2
#define MATSZ (BB*CC*CC)

#define PIT 136               // smem pitch (floats): 136%32==8 -> conflict-free fragment LDS
#define CHK 16                // K-depth per chunk
#define ARR (CHK*PIT)         // 2176 floats per array
#define STG (4*ARR)           // sAh, sAl, sBh, sBl
#define SMEM_BYTES (2*STG*4)  // 69632 B (double buffered)

// ---------------- scratch ----------------
__device__ float g_A[MATSZ];
__device__ float g_B0[MATSZ];
__device__ float g_B1[MATSZ];
__device__ float g_Y0[MATSZ];
__device__ float g_Y1[MATSZ];
__device__ float g_Z0[MATSZ];
__device__ float g_Z1[MATSZ];
__device__ float g_s[BB*CC];
__device__ float g_q[BB*CC];
__device__ float g_tr[BB];

// ---------------- helpers ----------------
__device__ __forceinline__ unsigned f2tf(float f) {
    unsigned r;
    asm("cvt.rna.tf32.f32 %0, %1;" : "=r"(r) : "f"(f));
    return r;
}

__device__ __forceinline__ void mma8(float* c, const unsigned* a, const unsigned* b) {
    asm volatile(
        "mma.sync.aligned.m16n8k8.row.col.f32.tf32.tf32.f32 "
        "{%0,%1,%2,%3}, {%4,%5,%6,%7}, {%8,%9}, {%0,%1,%2,%3};"
        : "+f"(c[0]), "+f"(c[1]), "+f"(c[2]), "+f"(c[3])
        : "r"(a[0]), "r"(a[1]), "r"(a[2]), "r"(a[3]), "r"(b[0]), "r"(b[1]));
}

// ---------------- chunk store: thread (rr = tid&127, q = tid>>7) ----------------
// layout: sAh[k][row] pitch PIT. STS banks = row (consecutive per warp) -> conflict-free.
__device__ __forceinline__ void sts_chunk(unsigned* st, int rr, int q, float4 av, float4 bv) {
    unsigned* sAh = st;
    unsigned* sAl = st + ARR;
    unsigned* sBh = st + 2 * ARR;
    unsigned* sBl = st + 3 * ARR;
    float va[4] = {av.x, av.y, av.z, av.w};
    float vb[4] = {bv.x, bv.y, bv.z, bv.w};
#pragma unroll
    for (int e = 0; e < 4; ++e) {
        int k = q * 4 + e;
        unsigned ha = f2tf(va[e]);
        unsigned hb = f2tf(vb[e]);
        sAh[k * PIT + rr] = ha;
        sAl[k * PIT + rr] = f2tf(va[e] - __uint_as_float(ha));
        sBh[k * PIT + rr] = hb;
        sBl[k * PIT + rr] = f2tf(vb[e] - __uint_as_float(hb));
    }
}

// ---------------- per-warp compute on one chunk (2 k-steps of 8) ----------------
// warp tile 32x32: it in 0..1 (16-row mma tiles), jt in 0..3 (8-col mma tiles)
__device__ __forceinline__ void compute_chunk(const unsigned* st, float acc[2][4][4],
                                              int wm, int wn, int g, int t) {
    const unsigned* sAh = st;
    const unsigned* sAl = st + ARR;
    const unsigned* sBh = st + 2 * ARR;
    const unsigned* sBl = st + 3 * ARR;
#pragma unroll
    for (int ks = 0; ks < 2; ++ks) {
        int kt = ks * 8 + t;
        unsigned ah[2][4], al[2][4], bh[4][2], bl[4][2];
#pragma unroll
        for (int it = 0; it < 2; ++it) {
            int m0 = wm * 32 + it * 16 + g;
            ah[it][0] = sAh[kt * PIT + m0];
            ah[it][1] = sAh[kt * PIT + m0 + 8];
            ah[it][2] = sAh[(kt + 4) * PIT + m0];
            ah[it][3] = sAh[(kt + 4) * PIT + m0 + 8];
            al[it][0] = sAl[kt * PIT + m0];
            al[it][1] = sAl[kt * PIT + m0 + 8];
            al[it][2] = sAl[(kt + 4) * PIT + m0];
            al[it][3] = sAl[(kt + 4) * PIT + m0 + 8];
        }
#pragma unroll
        for (int jt = 0; jt < 4; ++jt) {
            int n0 = wn * 32 + jt * 8 + g;
            bh[jt][0] = sBh[kt * PIT + n0];
            bh[jt][1] = sBh[(kt + 4) * PIT + n0];
            bl[jt][0] = sBl[kt * PIT + n0];
            bl[jt][1] = sBl[(kt + 4) * PIT + n0];
        }
#pragma unroll
        for (int it = 0; it < 2; ++it)
#pragma unroll
            for (int jt = 0; jt < 4; ++jt) {
                mma8(acc[it][jt], ah[it], bh[jt]);
                mma8(acc[it][jt], ah[it], bl[jt]);
                mma8(acc[it][jt], al[it], bh[jt]);
            }
    }
}

// ---------------- pipelined mainloop: one __syncthreads per chunk ----------------
__device__ __forceinline__ void run_loop(unsigned* sm, const float* gA, const float* gB,
                                         int strA, int strB, int nch, float acc[2][4][4],
                                         int wm, int wn, int g, int t, int rr, int q) {
    const float* pA = gA + (size_t)rr * strA + q * 4;
    const float* pB = gB + (size_t)rr * strB + q * 4;
    float4 va = *(const float4*)pA;
    float4 vb = *(const float4*)pB;
    sts_chunk(sm, rr, q, va, vb);                 // chunk 0 -> buf 0
    if (nch > 1) {
        va = *(const float4*)(pA + CHK);
        vb = *(const float4*)(pB + CHK);
    }
    __syncthreads();
#pragma unroll 2
    for (int s = 0; s < nch; ++s) {
        if (s + 1 < nch) sts_chunk(sm + ((s + 1) & 1) * STG, rr, q, va, vb);
        if (s + 2 < nch) {
            va = *(const float4*)(pA + (s + 2) * CHK);
            vb = *(const float4*)(pB + (s + 2) * CHK);
        }
        compute_chunk(sm + (s & 1) * STG, acc, wm, wn, g, t);
        __syncthreads();
    }
}

// ---------------- gram: A = (XX^T/n - ss^T/n^2)/tr ; B0 = 1.5I - 0.5A ----------------
__global__ __launch_bounds__(512, 1) void gram_mma(const float* __restrict__ X,
                                                   const float* __restrict__ sv,
                                                   const float* __restrict__ trv,
                                                   float* __restrict__ Ao,
                                                   float* __restrict__ B0o) {
    extern __shared__ unsigned sm[];
    int b = blockIdx.z, tile = blockIdx.x;
    int i0 = (tile == 2) ? 128 : 0, j0 = (tile != 0) ? 128 : 0;
    bool mirror = (tile == 1);
    int tid = threadIdx.x;
    int warp = tid >> 5, lane = tid & 31;
    int wm = warp >> 2, wn = warp & 3, g = lane >> 2, t = lane & 3;
    int rr = tid & 127, q = tid >> 7;
    float acc[2][4][4] = {};

    const float* Xb = X + (size_t)b * CC * NN;
    run_loop(sm, Xb + (size_t)i0 * NN, Xb + (size_t)j0 * NN, NN, NN, NN / CHK,
             acc, wm, wn, g, t, rr, q);

    const float inv_n = 1.0f / (float)NN;
    const float inv_n2 = inv_n * inv_n;
    float invtr = 1.0f / trv[b];
    float* Ab = Ao + (size_t)b * CC * CC;
    float* Bb = B0o + (size_t)b * CC * CC;
#pragma unroll
    for (int it = 0; it < 2; ++it)
#pragma unroll
        for (int jt = 0; jt < 4; ++jt) {
            int gi = i0 + wm * 32 + it * 16 + g;
            int gj = j0 + wn * 32 + jt * 8 + 2 * t;
            float* ca = acc[it][jt];
#pragma unroll
            for (int h = 0; h < 2; ++h) {
                int r = gi + h * 8;
                float si = sv[b * CC + r];
                float sj0 = sv[b * CC + gj], sj1 = sv[b * CC + gj + 1];
                float a0 = (ca[h * 2 + 0] * inv_n - si * sj0 * inv_n2) * invtr;
                float a1 = (ca[h * 2 + 1] * inv_n - si * sj1 * inv_n2) * invtr;
                float w0 = (r == gj ? 1.5f : 0.0f) - 0.5f * a0;
                float w1 = (r == gj + 1 ? 1.5f : 0.0f) - 0.5f * a1;
                *(float2*)&Ab[(size_t)r * CC + gj] = make_float2(a0, a1);
                *(float2*)&Bb[(size_t)r * CC + gj] = make_float2(w0, w1);
                if (mirror) {
                    Ab[(size_t)gj * CC + r] = a0;
                    Ab[(size_t)(gj + 1) * CC + r] = a1;
                    Bb[(size_t)gj * CC + r] = w0;
                    Bb[(size_t)(gj + 1) * CC + r] = w1;
                }
            }
        }
}

// ---------------- NS GEMM: EPI 0: C=A@B   EPI 1: C=1.5I-0.5(A@B)   EPI 2: triuvec ----------------
template <int EPI>
__global__ __launch_bounds__(512, 1) void ns_mma(const float* __restrict__ Ag,
                                                 const float* __restrict__ Bg,
                                                 float* __restrict__ Cg,
                                                 const float* __restrict__ trv,
                                                 float* __restrict__ outg) {
    extern __shared__ unsigned sm[];
    int b = blockIdx.z, tile = blockIdx.x;
    int i0 = (tile == 2) ? 128 : 0, j0 = (tile != 0) ? 128 : 0;
    bool mirror = (tile == 1);
    int tid = threadIdx.x;
    int warp = tid >> 5, lane = tid & 31;
    int wm = warp >> 2, wn = warp & 3, g = lane >> 2, t = lane & 3;
    int rr = tid & 127, q = tid >> 7;
    float acc[2][4][4] = {};

    // operands symmetric (polynomials in A): rows of B serve as K-major B^T
    run_loop(sm, Ag + (size_t)b * CC * CC + (size_t)i0 * CC,
             Bg + (size_t)b * CC * CC + (size_t)j0 * CC, CC, CC, CC / CHK,
             acc, wm, wn, g, t, rr, q);

    float* Cb = Cg + (size_t)b * CC * CC;
    float scale = (EPI == 2) ? sqrtf(trv[b]) : 0.f;
#pragma unroll
    for (int it = 0; it < 2; ++it)
#pragma unroll
        for (int jt = 0; jt < 4; ++jt) {
            int gi = i0 + wm * 32 + it * 16 + g;
            int gj = j0 + wn * 32 + jt * 8 + 2 * t;
            float* ca = acc[it][jt];
#pragma unroll
            for (int h = 0; h < 2; ++h) {
                int r = gi + h * 8;
                float v0 = ca[h * 2 + 0], v1 = ca[h * 2 + 1];
                if (EPI == 0) {
                    *(float2*)&Cb[(size_t)r * CC + gj] = make_float2(v0, v1);
                    if (mirror) {
                        Cb[(size_t)gj * CC + r] = v0;
                        Cb[(size_t)(gj + 1) * CC + r] = v1;
                    }
                } else if (EPI == 1) {
                    float w0 = (r == gj ? 1.5f : 0.0f) - 0.5f * v0;
                    float w1 = (r == gj + 1 ? 1.5f : 0.0f) - 0.5f * v1;
                    *(float2*)&Cb[(size_t)r * CC + gj] = make_float2(w0, w1);
                    if (mirror) {
                        Cb[(size_t)gj * CC + r] = w0;
                        Cb[(size_t)(gj + 1) * CC + r] = w1;
                    }
                } else {
                    int base = r * CC - (r * (r - 1)) / 2 - r;
                    if (gj >= r) outg[(size_t)b * OUTC + base + gj] = v0 * scale;
                    if (gj + 1 >= r) outg[(size_t)b * OUTC + base + gj + 1] = v1 * scale;
                }
            }
        }
}

// ---------------- row sums + sumsq ----------------
__global__ __launch_bounds__(256) void rowsumq_kernel(const float* __restrict__ X,
                                                      float* __restrict__ s,
                                                      float* __restrict__ q) {
    int c = blockIdx.x, b = blockIdx.y;
    const float4* row = (const float4*)(X + ((size_t)b * CC + c) * NN);
    float acc = 0.f, accq = 0.f;
    for (int i = threadIdx.x; i < NN / 4; i += 256) {
        float4 v = row[i];
        acc += v.x + v.y + v.z + v.w;
        accq += v.x * v.x + v.y * v.y + v.z * v.z + v.w * v.w;
    }
    __shared__ float ss[256], sq[256];
    ss[threadIdx.x] = acc;
    sq[threadIdx.x] = accq;
    __syncthreads();
    for (int st = 128; st > 0; st >>= 1) {
        if (threadIdx.x < st) {
            ss[threadIdx.x] += ss[threadIdx.x + st];
            sq[threadIdx.x] += sq[threadIdx.x + st];
        }
        __syncthreads();
    }
    if (threadIdx.x == 0) {
        s[b * CC + c] = ss[0];
        q[b * CC + c] = sq[0];
    }
}

__global__ __launch_bounds__(256) void trred_kernel(const float* __restrict__ s,
                                                    const float* __restrict__ q,
                                                    float* __restrict__ tr) {
    int b = blockIdx.x, c = threadIdx.x;
    const float inv_n = 1.0f / (float)NN;
    const float inv_n2 = inv_n * inv_n;
    float sv = s[b * CC + c];
    float v = q[b * CC + c] * inv_n - sv * sv * inv_n2;
    __shared__ float sm[256];
    sm[c] = v;
    __syncthreads();
    for (int st = 128; st > 0; st >>= 1) {
        if (c < st) sm[c] += sm[c + st];
        __syncthreads();
    }
    if (c == 0) tr[b] = sm[0];
}

// ---------------- launch ----------------
extern "C" void kernel_launch(void* const* d_in, const int* in_sizes, int n_in,
                              void* d_out, int out_size) {
    const float* x = (const float*)d_in[0];
    float* out = (float*)d_out;

    float *A, *B0, *B1, *Y0, *Y1, *Z0, *Z1, *s, *q, *tr;
    cudaGetSymbolAddress((void**)&A, g_A);
    cudaGetSymbolAddress((void**)&B0, g_B0);
    cudaGetSymbolAddress((void**)&B1, g_B1);
    cudaGetSymbolAddress((void**)&Y0, g_Y0);
    cudaGetSymbolAddress((void**)&Y1, g_Y1);
    cudaGetSymbolAddress((void**)&Z0, g_Z0);
    cudaGetSymbolAddress((void**)&Z1, g_Z1);
    cudaGetSymbolAddress((void**)&s, g_s);
    cudaGetSymbolAddress((void**)&q, g_q);
    cudaGetSymbolAddress((void**)&tr, g_tr);

    cudaFuncSetAttribute(gram_mma, cudaFuncAttributeMaxDynamicSharedMemorySize, SMEM_BYTES);
    cudaFuncSetAttribute(ns_mma<0>, cudaFuncAttributeMaxDynamicSharedMemorySize, SMEM_BYTES);
    cudaFuncSetAttribute(ns_mma<1>, cudaFuncAttributeMaxDynamicSharedMemorySize, SMEM_BYTES);
    cudaFuncSetAttribute(ns_mma<2>, cudaFuncAttributeMaxDynamicSharedMemorySize, SMEM_BYTES);

    rowsumq_kernel<<<dim3(CC, BB), 256>>>(x, s, q);
    trred_kernel<<<BB, 256>>>(s, q, tr);

    dim3 gg(3, 1, BB);
    gram_mma<<<gg, 512, SMEM_BYTES>>>(x, s, tr, A, B0);

    ns_mma<0><<<gg, 512, SMEM_BYTES>>>(A, B0, Y0, nullptr, nullptr);
    // iter 1
    ns_mma<1><<<gg, 512, SMEM_BYTES>>>(B0, Y0, B1, nullptr, nullptr);
    ns_mma<0><<<gg, 512, SMEM_BYTES>>>(Y0, B1, Y1, nullptr, nullptr);
    ns_mma<0><<<gg, 512, SMEM_BYTES>>>(B1, B0, Z0, nullptr, nullptr);
    // iter 2
    ns_mma<1><<<gg, 512, SMEM_BYTES>>>(Z0, Y1, B0, nullptr, nullptr);
    ns_mma<0><<<gg, 512, SMEM_BYTES>>>(Y1, B0, Y0, nullptr, nullptr);
    ns_mma<0><<<gg, 512, SMEM_BYTES>>>(B0, Z0, Z1, nullptr, nullptr);
    // iter 3
    ns_mma<1><<<gg, 512, SMEM_BYTES>>>(Z1, Y0, B1, nullptr, nullptr);
    ns_mma<0><<<gg, 512, SMEM_BYTES>>>(Y0, B1, Y1, nullptr, nullptr);
    ns_mma<0><<<gg, 512, SMEM_BYTES>>>(B1, Z1, Z0, nullptr, nullptr);
    // iter 4 (Z update dead -> dropped)
    ns_mma<1><<<gg, 512, SMEM_BYTES>>>(Z0, Y1, B0, nullptr, nullptr);
    ns_mma<2><<<gg, 512, SMEM_BYTES>>>(Y1, B0, nullptr, tr, out);
}

// round 5
// speedup vs baseline: 2.1911x; 1.3266x over previous
#include <cuda_runtime.h>
#include <cuda_fp16.h>
#include <math.h>

#define BB 32
#define CC 256
#define NN 3136
#define OUTC 32896            // 256*257/2
#define MATSZ (BB*CC*CC)

#define PITW 136              // words per k-pair row (128 rows + pad); 136%32==8 -> conflict-free
#define CHK 16                // K elements per chunk (= 8 half2 words)
#define ARRW (8*PITW)         // 1088 words per array per chunk
#define STGW (4*ARRW)         // sAh, sAl, sBh, sBl
#define SSCALE 64.0f
#define INVS2 (1.0f/(SSCALE*SSCALE))

// ---------------- scratch ----------------
__device__ float g_A[MATSZ];
__device__ float g_B0[MATSZ];
__device__ float g_B1[MATSZ];
__device__ float g_Y0[MATSZ];
__device__ float g_Y1[MATSZ];
__device__ float g_Z0[MATSZ];
__device__ float g_Z1[MATSZ];
__device__ float g_s[BB*CC];
__device__ float g_q[BB*CC];
__device__ float g_tr[BB];

// ---------------- helpers ----------------
__device__ __forceinline__ void mma16(float* c, const unsigned* a, const unsigned* b) {
    asm volatile(
        "mma.sync.aligned.m16n8k16.row.col.f32.f16.f16.f32 "
        "{%0,%1,%2,%3}, {%4,%5,%6,%7}, {%8,%9}, {%0,%1,%2,%3};"
        : "+f"(c[0]), "+f"(c[1]), "+f"(c[2]), "+f"(c[3])
        : "r"(a[0]), "r"(a[1]), "r"(a[2]), "r"(a[3]), "r"(b[0]), "r"(b[1]));
}

// split x -> (hi, lo) fp16 pair after scaling by SSCALE
__device__ __forceinline__ void split2(float x0, float x1, unsigned& hi, unsigned& lo) {
    float s0 = x0 * SSCALE, s1 = x1 * SSCALE;
    __half h0 = __float2half_rn(s0), h1 = __float2half_rn(s1);
    __half l0 = __float2half_rn(s0 - __half2float(h0));
    __half l1 = __float2half_rn(s1 - __half2float(h1));
    __half2 hh = __halves2half2(h0, h1), ll = __halves2half2(l0, l1);
    hi = *(unsigned*)&hh;
    lo = *(unsigned*)&ll;
}

// ---------------- chunk store: thread (rr = tid&127, q = tid>>7 in 0..3) ----------------
__device__ __forceinline__ void sts_chunk(unsigned* st, int rr, int q, float4 av, float4 bv) {
    unsigned* sAh = st;
    unsigned* sAl = st + ARRW;
    unsigned* sBh = st + 2 * ARRW;
    unsigned* sBl = st + 3 * ARRW;
    int kw0 = q * 2, kw1 = q * 2 + 1;
    unsigned h, l;
    split2(av.x, av.y, h, l); sAh[kw0 * PITW + rr] = h; sAl[kw0 * PITW + rr] = l;
    split2(av.z, av.w, h, l); sAh[kw1 * PITW + rr] = h; sAl[kw1 * PITW + rr] = l;
    split2(bv.x, bv.y, h, l); sBh[kw0 * PITW + rr] = h; sBl[kw0 * PITW + rr] = l;
    split2(bv.z, bv.w, h, l); sBh[kw1 * PITW + rr] = h; sBl[kw1 * PITW + rr] = l;
}

// ---------------- per-warp compute on one chunk (one k16 step) ----------------
// warp tile 32x32: it in 0..1 (16-row tiles), jt in 0..3 (8-col tiles)
__device__ __forceinline__ void compute_chunk(const unsigned* st, float acc[2][4][4],
                                              int wm, int wn, int g, int t) {
    const unsigned* sAh = st;
    const unsigned* sAl = st + ARRW;
    const unsigned* sBh = st + 2 * ARRW;
    const unsigned* sBl = st + 3 * ARRW;
    unsigned ah[2][4], al[2][4], bh[4][2], bl[4][2];
#pragma unroll
    for (int it = 0; it < 2; ++it) {
        int m0 = wm * 32 + it * 16 + g;
        ah[it][0] = sAh[t * PITW + m0];
        ah[it][1] = sAh[t * PITW + m0 + 8];
        ah[it][2] = sAh[(t + 4) * PITW + m0];
        ah[it][3] = sAh[(t + 4) * PITW + m0 + 8];
        al[it][0] = sAl[t * PITW + m0];
        al[it][1] = sAl[t * PITW + m0 + 8];
        al[it][2] = sAl[(t + 4) * PITW + m0];
        al[it][3] = sAl[(t + 4) * PITW + m0 + 8];
    }
#pragma unroll
    for (int jt = 0; jt < 4; ++jt) {
        int n0 = wn * 32 + jt * 8 + g;
        bh[jt][0] = sBh[t * PITW + n0];
        bh[jt][1] = sBh[(t + 4) * PITW + n0];
        bl[jt][0] = sBl[t * PITW + n0];
        bl[jt][1] = sBl[(t + 4) * PITW + n0];
    }
#pragma unroll
    for (int it = 0; it < 2; ++it)
#pragma unroll
        for (int jt = 0; jt < 4; ++jt) {
            mma16(acc[it][jt], ah[it], bh[jt]);
            mma16(acc[it][jt], ah[it], bl[jt]);
            mma16(acc[it][jt], al[it], bh[jt]);
        }
}

// ---------------- pipelined mainloop: one __syncthreads per chunk ----------------
__device__ __forceinline__ void run_loop(unsigned* sm, const float* gA, const float* gB,
                                         int strA, int strB, int nch, float acc[2][4][4],
                                         int wm, int wn, int g, int t, int rr, int q) {
    const float* pA = gA + (size_t)rr * strA + q * 4;
    const float* pB = gB + (size_t)rr * strB + q * 4;
    float4 va = *(const float4*)pA;
    float4 vb = *(const float4*)pB;
    sts_chunk(sm, rr, q, va, vb);
    if (nch > 1) {
        va = *(const float4*)(pA + CHK);
        vb = *(const float4*)(pB + CHK);
    }
    __syncthreads();
#pragma unroll 2
    for (int s = 0; s < nch; ++s) {
        if (s + 1 < nch) sts_chunk(sm + ((s + 1) & 1) * STGW, rr, q, va, vb);
        if (s + 2 < nch) {
            va = *(const float4*)(pA + (s + 2) * CHK);
            vb = *(const float4*)(pB + (s + 2) * CHK);
        }
        compute_chunk(sm + (s & 1) * STGW, acc, wm, wn, g, t);
        __syncthreads();
    }
}

// ---------------- gram: A = (XX^T/n - ss^T/n^2)/tr ; B0 = 1.5 I - 0.5 A ----------------
__global__ __launch_bounds__(512, 1) void gram_mma(const float* __restrict__ X,
                                                   const float* __restrict__ sv,
                                                   const float* __restrict__ trv,
                                                   float* __restrict__ Ao,
                                                   float* __restrict__ B0o) {
    __shared__ unsigned sm[2 * STGW];
    int b = blockIdx.z, tile = blockIdx.x;
    int i0 = (tile == 2) ? 128 : 0, j0 = (tile != 0) ? 128 : 0;
    bool mirror = (tile == 1);
    int tid = threadIdx.x;
    int warp = tid >> 5, lane = tid & 31;
    int wm = warp >> 2, wn = warp & 3, g = lane >> 2, t = lane & 3;
    int rr = tid & 127, q = tid >> 7;
    float acc[2][4][4] = {};

    const float* Xb = X + (size_t)b * CC * NN;
    run_loop(sm, Xb + (size_t)i0 * NN, Xb + (size_t)j0 * NN, NN, NN, NN / CHK,
             acc, wm, wn, g, t, rr, q);

    const float inv_n = 1.0f / (float)NN;
    const float inv_n2 = inv_n * inv_n;
    float invtr = 1.0f / trv[b];
    float c1 = INVS2 * inv_n * invtr;      // applies to mma result
    float c2 = inv_n2 * invtr;             // applies to si*sj
    float* Ab = Ao + (size_t)b * CC * CC;
    float* Bb = B0o + (size_t)b * CC * CC;
#pragma unroll
    for (int it = 0; it < 2; ++it)
#pragma unroll
        for (int jt = 0; jt < 4; ++jt) {
            int gi = i0 + wm * 32 + it * 16 + g;
            int gj = j0 + wn * 32 + jt * 8 + 2 * t;
            float* ca = acc[it][jt];
#pragma unroll
            for (int h = 0; h < 2; ++h) {
                int r = gi + h * 8;
                float si = sv[b * CC + r];
                float a0 = ca[h * 2 + 0] * c1 - si * sv[b * CC + gj] * c2;
                float a1 = ca[h * 2 + 1] * c1 - si * sv[b * CC + gj + 1] * c2;
                float w0 = (r == gj ? 1.5f : 0.0f) - 0.5f * a0;
                float w1 = (r == gj + 1 ? 1.5f : 0.0f) - 0.5f * a1;
                *(float2*)&Ab[(size_t)r * CC + gj] = make_float2(a0, a1);
                *(float2*)&Bb[(size_t)r * CC + gj] = make_float2(w0, w1);
                if (mirror) {
                    Ab[(size_t)gj * CC + r] = a0;
                    Ab[(size_t)(gj + 1) * CC + r] = a1;
                    Bb[(size_t)gj * CC + r] = w0;
                    Bb[(size_t)(gj + 1) * CC + r] = w1;
                }
            }
        }
}

// ---------------- NS GEMM: EPI 0: C=A@B   EPI 1: C=1.5I-0.5(A@B)   EPI 2: triuvec ----------------
template <int EPI>
__global__ __launch_bounds__(512, 1) void ns_mma(const float* __restrict__ Ag,
                                                 const float* __restrict__ Bg,
                                                 float* __restrict__ Cg,
                                                 const float* __restrict__ trv,
                                                 float* __restrict__ outg) {
    __shared__ unsigned sm[2 * STGW];
    int b = blockIdx.z, tile = blockIdx.x;
    int i0 = (tile == 2) ? 128 : 0, j0 = (tile != 0) ? 128 : 0;
    bool mirror = (tile == 1);
    int tid = threadIdx.x;
    int warp = tid >> 5, lane = tid & 31;
    int wm = warp >> 2, wn = warp & 3, g = lane >> 2, t = lane & 3;
    int rr = tid & 127, q = tid >> 7;
    float acc[2][4][4] = {};

    // operands symmetric (polynomials in A): rows of B serve as K-major B^T
    run_loop(sm, Ag + (size_t)b * CC * CC + (size_t)i0 * CC,
             Bg + (size_t)b * CC * CC + (size_t)j0 * CC, CC, CC, CC / CHK,
             acc, wm, wn, g, t, rr, q);

    float* Cb = Cg + (size_t)b * CC * CC;
    float scale = (EPI == 2) ? sqrtf(trv[b]) * INVS2 : INVS2;
#pragma unroll
    for (int it = 0; it < 2; ++it)
#pragma unroll
        for (int jt = 0; jt < 4; ++jt) {
            int gi = i0 + wm * 32 + it * 16 + g;
            int gj = j0 + wn * 32 + jt * 8 + 2 * t;
            float* ca = acc[it][jt];
#pragma unroll
            for (int h = 0; h < 2; ++h) {
                int r = gi + h * 8;
                float v0 = ca[h * 2 + 0] * scale, v1 = ca[h * 2 + 1] * scale;
                if (EPI == 0) {
                    *(float2*)&Cb[(size_t)r * CC + gj] = make_float2(v0, v1);
                    if (mirror) {
                        Cb[(size_t)gj * CC + r] = v0;
                        Cb[(size_t)(gj + 1) * CC + r] = v1;
                    }
                } else if (EPI == 1) {
                    float w0 = (r == gj ? 1.5f : 0.0f) - 0.5f * v0;
                    float w1 = (r == gj + 1 ? 1.5f : 0.0f) - 0.5f * v1;
                    *(float2*)&Cb[(size_t)r * CC + gj] = make_float2(w0, w1);
                    if (mirror) {
                        Cb[(size_t)gj * CC + r] = w0;
                        Cb[(size_t)(gj + 1) * CC + r] = w1;
                    }
                } else {
                    int base = r * CC - (r * (r - 1)) / 2 - r;
                    if (gj >= r) outg[(size_t)b * OUTC + base + gj] = v0;
                    if (gj + 1 >= r) outg[(size_t)b * OUTC + base + gj + 1] = v1;
                }
            }
        }
}

// ---------------- row sums + sumsq ----------------
__global__ __launch_bounds__(256) void rowsumq_kernel(const float* __restrict__ X,
                                                      float* __restrict__ s,
                                                      float* __restrict__ q) {
    int c = blockIdx.x, b = blockIdx.y;
    const float4* row = (const float4*)(X + ((size_t)b * CC + c) * NN);
    float acc = 0.f, accq = 0.f;
    for (int i = threadIdx.x; i < NN / 4; i += 256) {
        float4 v = row[i];
        acc += v.x + v.y + v.z + v.w;
        accq += v.x * v.x + v.y * v.y + v.z * v.z + v.w * v.w;
    }
    __shared__ float ss[256], sq[256];
    ss[threadIdx.x] = acc;
    sq[threadIdx.x] = accq;
    __syncthreads();
    for (int st = 128; st > 0; st >>= 1) {
        if (threadIdx.x < st) {
            ss[threadIdx.x] += ss[threadIdx.x + st];
            sq[threadIdx.x] += sq[threadIdx.x + st];
        }
        __syncthreads();
    }
    if (threadIdx.x == 0) {
        s[b * CC + c] = ss[0];
        q[b * CC + c] = sq[0];
    }
}

__global__ __launch_bounds__(256) void trred_kernel(const float* __restrict__ s,
                                                    const float* __restrict__ q,
                                                    float* __restrict__ tr) {
    int b = blockIdx.x, c = threadIdx.x;
    const float inv_n = 1.0f / (float)NN;
    const float inv_n2 = inv_n * inv_n;
    float sv = s[b * CC + c];
    float v = q[b * CC + c] * inv_n - sv * sv * inv_n2;
    __shared__ float sm[256];
    sm[c] = v;
    __syncthreads();
    for (int st = 128; st > 0; st >>= 1) {
        if (c < st) sm[c] += sm[c + st];
        __syncthreads();
    }
    if (c == 0) tr[b] = sm[0];
}

// ---------------- launch ----------------
extern "C" void kernel_launch(void* const* d_in, const int* in_sizes, int n_in,
                              void* d_out, int out_size) {
    const float* x = (const float*)d_in[0];
    float* out = (float*)d_out;

    float *A, *B0, *B1, *Y0, *Y1, *Z0, *Z1, *s, *q, *tr;
    cudaGetSymbolAddress((void**)&A, g_A);
    cudaGetSymbolAddress((void**)&B0, g_B0);
    cudaGetSymbolAddress((void**)&B1, g_B1);
    cudaGetSymbolAddress((void**)&Y0, g_Y0);
    cudaGetSymbolAddress((void**)&Y1, g_Y1);
    cudaGetSymbolAddress((void**)&Z0, g_Z0);
    cudaGetSymbolAddress((void**)&Z1, g_Z1);
    cudaGetSymbolAddress((void**)&s, g_s);
    cudaGetSymbolAddress((void**)&q, g_q);
    cudaGetSymbolAddress((void**)&tr, g_tr);

    rowsumq_kernel<<<dim3(CC, BB), 256>>>(x, s, q);
    trred_kernel<<<BB, 256>>>(s, q, tr);

    dim3 gg(3, 1, BB);
    gram_mma<<<gg, 512>>>(x, s, tr, A, B0);

    ns_mma<0><<<gg, 512>>>(A, B0, Y0, nullptr, nullptr);
    // iter 1
    ns_mma<1><<<gg, 512>>>(B0, Y0, B1, nullptr, nullptr);
    ns_mma<0><<<gg, 512>>>(Y0, B1, Y1, nullptr, nullptr);
    ns_mma<0><<<gg, 512>>>(B1, B0, Z0, nullptr, nullptr);
    // iter 2
    ns_mma<1><<<gg, 512>>>(Z0, Y1, B0, nullptr, nullptr);
    ns_mma<0><<<gg, 512>>>(Y1, B0, Y0, nullptr, nullptr);
    ns_mma<0><<<gg, 512>>>(B0, Z0, Z1, nullptr, nullptr);
    // iter 3
    ns_mma<1><<<gg, 512>>>(Z1, Y0, B1, nullptr, nullptr);
    ns_mma<0><<<gg, 512>>>(Y0, B1, Y1, nullptr, nullptr);
    ns_mma<0><<<gg, 512>>>(B1, Z1, Z0, nullptr, nullptr);
    // iter 4 (Z update dead -> dropped)
    ns_mma<1><<<gg, 512>>>(Z0, Y1, B0, nullptr, nullptr);
    ns_mma<2><<<gg, 512>>>(Y1, B0, nullptr, tr, out);
}

// round 6
// speedup vs baseline: 3.4012x; 1.5523x over previous
#include <cuda_runtime.h>
#include <cuda_fp16.h>
#include <math.h>
#include <stdint.h>

#define BB 32
#define CC 256
#define NN 3136
#define OUTC 32896            // 256*257/2
#define MATSZ (BB*CC*CC)

#define CHK 32                // K elements per chunk
#define PITI 36               // words per row: 4 ksubs * (hi 16B + lo 16B) + 16B pad = 144B
#define MATW (128*PITI)       // 4608 words per matrix per stage
#define STGW2 (2*MATW)        // 9216 words per stage (A + B)
#define SMEM_BYTES (2*STGW2*4)  // 73728 B double-buffered
#define SSCALE 64.0f
#define INVS2 (1.0f/(SSCALE*SSCALE))

// ---------------- scratch ----------------
__device__ float g_A[MATSZ];
__device__ float g_B0[MATSZ];
__device__ float g_B1[MATSZ];
__device__ float g_Y0[MATSZ];
__device__ float g_Y1[MATSZ];
__device__ float g_Z0[MATSZ];
__device__ float g_Z1[MATSZ];
__device__ float g_s[BB*CC];
__device__ float g_q[BB*CC];
__device__ float g_tr[BB];

// ---------------- primitives ----------------
__device__ __forceinline__ uint32_t smem_u32(const void* p) {
    uint32_t a;
    asm("{ .reg .u64 t; cvta.to.shared.u64 t, %1; cvt.u32.u64 %0, t; }" : "=r"(a) : "l"(p));
    return a;
}

__device__ __forceinline__ void mma16(float* c, const unsigned* a, const unsigned* b) {
    asm volatile(
        "mma.sync.aligned.m16n8k16.row.col.f32.f16.f16.f32 "
        "{%0,%1,%2,%3}, {%4,%5,%6,%7}, {%8,%9}, {%0,%1,%2,%3};"
        : "+f"(c[0]), "+f"(c[1]), "+f"(c[2]), "+f"(c[3])
        : "r"(a[0]), "r"(a[1]), "r"(a[2]), "r"(a[3]), "r"(b[0]), "r"(b[1]));
}

__device__ __forceinline__ void ldm4(unsigned r[4], uint32_t a) {
    asm volatile("ldmatrix.sync.aligned.m8n8.x4.shared.b16 {%0,%1,%2,%3}, [%4];"
                 : "=r"(r[0]), "=r"(r[1]), "=r"(r[2]), "=r"(r[3]) : "r"(a));
}

__device__ __forceinline__ void split2(float x0, float x1, unsigned& hi, unsigned& lo) {
    float s0 = x0 * SSCALE, s1 = x1 * SSCALE;
    __half h0 = __float2half_rn(s0), h1 = __float2half_rn(s1);
    __half l0 = __float2half_rn(s0 - __half2float(h0));
    __half l1 = __float2half_rn(s1 - __half2float(h1));
    __half2 hh = __halves2half2(h0, h1), ll = __halves2half2(l0, l1);
    hi = *(unsigned*)&hh;
    lo = *(unsigned*)&ll;
}

// row layout: [ksub 0..3][hi 4 words][lo 4 words], pitch 36 words (last 4 pad)
__device__ __forceinline__ void sts_row(unsigned* rowp, int q, float4 v) {
    unsigned h0, l0, h1, l1;
    split2(v.x, v.y, h0, l0);
    split2(v.z, v.w, h1, l1);
    int wo = (q >> 1) * 8 + 2 * (q & 1);
    *(uint2*)(rowp + wo) = make_uint2(h0, h1);
    *(uint2*)(rowp + wo + 4) = make_uint2(l0, l1);
}

__device__ __forceinline__ void sts_chunk(unsigned* stage, int rr, int q,
                                          float4 va0, float4 va1, float4 vb0, float4 vb1) {
    sts_row(stage + rr * PITI, q, va0);
    sts_row(stage + (rr + 64) * PITI, q, va1);
    sts_row(stage + MATW + rr * PITI, q, vb0);
    sts_row(stage + MATW + (rr + 64) * PITI, q, vb1);
}

// ---------------- per-warp compute on one CHK=32 chunk ----------------
__device__ __forceinline__ void compute_chunk(uint32_t aU, float acc[2][4][4],
                                              int wm, int wn, int lane) {
    uint32_t bU = aU + MATW * 4;
    int lr = lane & 7;
    int lt8 = (lane >> 3) & 1;
    int lkh = (lane >> 4) & 1;
    // A: tiles (rows m0+lt8*8, ksub+lkh); B: tiles (cols n0+lkh*8, ksub+lt8)
    uint32_t aA = aU + ((wm * 32 + lt8 * 8 + lr) * PITI + lkh * 8) * 4;
    uint32_t bA = bU + ((wn * 32 + lkh * 8 + lr) * PITI + lt8 * 8) * 4;
#pragma unroll
    for (int ks = 0; ks < 2; ++ks) {
        unsigned ah[2][4], al[2][4], bh[2][4], bl[2][4];
        uint32_t kb = ks * 64;  // 16 words
        ldm4(ah[0], aA + kb);
        ldm4(ah[1], aA + 2304 + kb);      // +16 rows * 144B
        ldm4(al[0], aA + kb + 16);
        ldm4(al[1], aA + 2304 + kb + 16);
        ldm4(bh[0], bA + kb);
        ldm4(bh[1], bA + 2304 + kb);      // +16 cols * 144B
        ldm4(bl[0], bA + kb + 16);
        ldm4(bl[1], bA + 2304 + kb + 16);
#pragma unroll
        for (int it = 0; it < 2; ++it)
#pragma unroll
            for (int jt = 0; jt < 4; ++jt) {
                const unsigned* bhp = &bh[jt >> 1][(jt & 1) * 2];
                const unsigned* blp = &bl[jt >> 1][(jt & 1) * 2];
                mma16(acc[it][jt], ah[it], bhp);
                mma16(acc[it][jt], ah[it], blp);
                mma16(acc[it][jt], al[it], bhp);
            }
    }
}

// ---------------- pipelined mainloop, one sync per chunk ----------------
__device__ __forceinline__ void run_loop(unsigned* sw, uint32_t smem_u,
                                         const float* gA, const float* gB,
                                         int strA, int strB, int nch, float acc[2][4][4],
                                         int wm, int wn, int lane, int rr, int q) {
    const float* pA0 = gA + (size_t)rr * strA + q * 4;
    const float* pA1 = gA + (size_t)(rr + 64) * strA + q * 4;
    const float* pB0 = gB + (size_t)rr * strB + q * 4;
    const float* pB1 = gB + (size_t)(rr + 64) * strB + q * 4;
    float4 va0 = *(const float4*)pA0;
    float4 va1 = *(const float4*)pA1;
    float4 vb0 = *(const float4*)pB0;
    float4 vb1 = *(const float4*)pB1;
    sts_chunk(sw, rr, q, va0, va1, vb0, vb1);
    if (nch > 1) {
        va0 = *(const float4*)(pA0 + CHK);
        va1 = *(const float4*)(pA1 + CHK);
        vb0 = *(const float4*)(pB0 + CHK);
        vb1 = *(const float4*)(pB1 + CHK);
    }
    __syncthreads();
    for (int s = 0; s < nch; ++s) {
        if (s + 1 < nch) sts_chunk(sw + ((s + 1) & 1) * STGW2, rr, q, va0, va1, vb0, vb1);
        if (s + 2 < nch) {
            int o = (s + 2) * CHK;
            va0 = *(const float4*)(pA0 + o);
            va1 = *(const float4*)(pA1 + o);
            vb0 = *(const float4*)(pB0 + o);
            vb1 = *(const float4*)(pB1 + o);
        }
        compute_chunk(smem_u + (s & 1) * STGW2 * 4, acc, wm, wn, lane);
        __syncthreads();
    }
}

// ---------------- gram: A = (XX^T/n - ss^T/n^2)/tr ; B0 = 1.5 I - 0.5 A ----------------
__global__ __launch_bounds__(512, 1) void gram_mma(const float* __restrict__ X,
                                                   const float* __restrict__ sv,
                                                   const float* __restrict__ trv,
                                                   float* __restrict__ Ao,
                                                   float* __restrict__ B0o) {
    extern __shared__ unsigned sw[];
    uint32_t smem_u = smem_u32(sw);
    int b = blockIdx.z, tile = blockIdx.x;
    int i0 = (tile == 2) ? 128 : 0, j0 = (tile != 0) ? 128 : 0;
    bool mirror = (tile == 1);
    int tid = threadIdx.x;
    int warp = tid >> 5, lane = tid & 31;
    int wm = warp >> 2, wn = warp & 3, g = lane >> 2, t = lane & 3;
    int rr = tid >> 3, q = tid & 7;
    float acc[2][4][4] = {};

    const float* Xb = X + (size_t)b * CC * NN;
    run_loop(sw, smem_u, Xb + (size_t)i0 * NN, Xb + (size_t)j0 * NN, NN, NN, NN / CHK,
             acc, wm, wn, lane, rr, q);

    const float inv_n = 1.0f / (float)NN;
    const float inv_n2 = inv_n * inv_n;
    float invtr = 1.0f / trv[b];
    float c1 = INVS2 * inv_n * invtr;
    float c2 = inv_n2 * invtr;
    float* Ab = Ao + (size_t)b * CC * CC;
    float* Bb = B0o + (size_t)b * CC * CC;
#pragma unroll
    for (int it = 0; it < 2; ++it)
#pragma unroll
        for (int jt = 0; jt < 4; ++jt) {
            int gi = i0 + wm * 32 + it * 16 + g;
            int gj = j0 + wn * 32 + jt * 8 + 2 * t;
            float* ca = acc[it][jt];
#pragma unroll
            for (int h = 0; h < 2; ++h) {
                int r = gi + h * 8;
                float si = sv[b * CC + r];
                float a0 = ca[h * 2 + 0] * c1 - si * sv[b * CC + gj] * c2;
                float a1 = ca[h * 2 + 1] * c1 - si * sv[b * CC + gj + 1] * c2;
                float w0 = (r == gj ? 1.5f : 0.0f) - 0.5f * a0;
                float w1 = (r == gj + 1 ? 1.5f : 0.0f) - 0.5f * a1;
                *(float2*)&Ab[(size_t)r * CC + gj] = make_float2(a0, a1);
                *(float2*)&Bb[(size_t)r * CC + gj] = make_float2(w0, w1);
                if (mirror) {
                    Ab[(size_t)gj * CC + r] = a0;
                    Ab[(size_t)(gj + 1) * CC + r] = a1;
                    Bb[(size_t)gj * CC + r] = w0;
                    Bb[(size_t)(gj + 1) * CC + r] = w1;
                }
            }
        }
}

// ---------------- NS GEMM: EPI 0: C=A@B   EPI 1: C=1.5I-0.5(A@B)   EPI 2: triuvec ----------------
template <int EPI>
__global__ __launch_bounds__(512, 1) void ns_mma(const float* __restrict__ Ag,
                                                 const float* __restrict__ Bg,
                                                 float* __restrict__ Cg,
                                                 const float* __restrict__ trv,
                                                 float* __restrict__ outg) {
    extern __shared__ unsigned sw[];
    uint32_t smem_u = smem_u32(sw);
    int b = blockIdx.z, tile = blockIdx.x;
    int i0 = (tile == 2) ? 128 : 0, j0 = (tile != 0) ? 128 : 0;
    bool mirror = (tile == 1);
    int tid = threadIdx.x;
    int warp = tid >> 5, lane = tid & 31;
    int wm = warp >> 2, wn = warp & 3, g = lane >> 2, t = lane & 3;
    int rr = tid >> 3, q = tid & 7;
    float acc[2][4][4] = {};

    // operands symmetric (polynomials in A): rows of B serve as K-major B^T
    run_loop(sw, smem_u, Ag + (size_t)b * CC * CC + (size_t)i0 * CC,
             Bg + (size_t)b * CC * CC + (size_t)j0 * CC, CC, CC, CC / CHK,
             acc, wm, wn, lane, rr, q);

    float* Cb = Cg + (size_t)b * CC * CC;
    float scale = (EPI == 2) ? sqrtf(trv[b]) * INVS2 : INVS2;
#pragma unroll
    for (int it = 0; it < 2; ++it)
#pragma unroll
        for (int jt = 0; jt < 4; ++jt) {
            int gi = i0 + wm * 32 + it * 16 + g;
            int gj = j0 + wn * 32 + jt * 8 + 2 * t;
            float* ca = acc[it][jt];
#pragma unroll
            for (int h = 0; h < 2; ++h) {
                int r = gi + h * 8;
                float v0 = ca[h * 2 + 0] * scale, v1 = ca[h * 2 + 1] * scale;
                if (EPI == 0) {
                    *(float2*)&Cb[(size_t)r * CC + gj] = make_float2(v0, v1);
                    if (mirror) {
                        Cb[(size_t)gj * CC + r] = v0;
                        Cb[(size_t)(gj + 1) * CC + r] = v1;
                    }
                } else if (EPI == 1) {
                    float w0 = (r == gj ? 1.5f : 0.0f) - 0.5f * v0;
                    float w1 = (r == gj + 1 ? 1.5f : 0.0f) - 0.5f * v1;
                    *(float2*)&Cb[(size_t)r * CC + gj] = make_float2(w0, w1);
                    if (mirror) {
                        Cb[(size_t)gj * CC + r] = w0;
                        Cb[(size_t)(gj + 1) * CC + r] = w1;
                    }
                } else {
                    int base = r * CC - (r * (r - 1)) / 2 - r;
                    if (gj >= r) outg[(size_t)b * OUTC + base + gj] = v0;
                    if (gj + 1 >= r) outg[(size_t)b * OUTC + base + gj + 1] = v1;
                }
            }
        }
}

// ---------------- row sums + sumsq ----------------
__global__ __launch_bounds__(256) void rowsumq_kernel(const float* __restrict__ X,
                                                      float* __restrict__ s,
                                                      float* __restrict__ q) {
    int c = blockIdx.x, b = blockIdx.y;
    const float4* row = (const float4*)(X + ((size_t)b * CC + c) * NN);
    float acc = 0.f, accq = 0.f;
    for (int i = threadIdx.x; i < NN / 4; i += 256) {
        float4 v = row[i];
        acc += v.x + v.y + v.z + v.w;
        accq += v.x * v.x + v.y * v.y + v.z * v.z + v.w * v.w;
    }
    __shared__ float ss[256], sq[256];
    ss[threadIdx.x] = acc;
    sq[threadIdx.x] = accq;
    __syncthreads();
    for (int st = 128; st > 0; st >>= 1) {
        if (threadIdx.x < st) {
            ss[threadIdx.x] += ss[threadIdx.x + st];
            sq[threadIdx.x] += sq[threadIdx.x + st];
        }
        __syncthreads();
    }
    if (threadIdx.x == 0) {
        s[b * CC + c] = ss[0];
        q[b * CC + c] = sq[0];
    }
}

__global__ __launch_bounds__(256) void trred_kernel(const float* __restrict__ s,
                                                    const float* __restrict__ q,
                                                    float* __restrict__ tr) {
    int b = blockIdx.x, c = threadIdx.x;
    const float inv_n = 1.0f / (float)NN;
    const float inv_n2 = inv_n * inv_n;
    float sv = s[b * CC + c];
    float v = q[b * CC + c] * inv_n - sv * sv * inv_n2;
    __shared__ float sm[256];
    sm[c] = v;
    __syncthreads();
    for (int st = 128; st > 0; st >>= 1) {
        if (c < st) sm[c] += sm[c + st];
        __syncthreads();
    }
    if (c == 0) tr[b] = sm[0];
}

// ---------------- launch ----------------
extern "C" void kernel_launch(void* const* d_in, const int* in_sizes, int n_in,
                              void* d_out, int out_size) {
    const float* x = (const float*)d_in[0];
    float* out = (float*)d_out;

    float *A, *B0, *B1, *Y0, *Y1, *Z0, *Z1, *s, *q, *tr;
    cudaGetSymbolAddress((void**)&A, g_A);
    cudaGetSymbolAddress((void**)&B0, g_B0);
    cudaGetSymbolAddress((void**)&B1, g_B1);
    cudaGetSymbolAddress((void**)&Y0, g_Y0);
    cudaGetSymbolAddress((void**)&Y1, g_Y1);
    cudaGetSymbolAddress((void**)&Z0, g_Z0);
    cudaGetSymbolAddress((void**)&Z1, g_Z1);
    cudaGetSymbolAddress((void**)&s, g_s);
    cudaGetSymbolAddress((void**)&q, g_q);
    cudaGetSymbolAddress((void**)&tr, g_tr);

    cudaFuncSetAttribute(gram_mma, cudaFuncAttributeMaxDynamicSharedMemorySize, SMEM_BYTES);
    cudaFuncSetAttribute(ns_mma<0>, cudaFuncAttributeMaxDynamicSharedMemorySize, SMEM_BYTES);
    cudaFuncSetAttribute(ns_mma<1>, cudaFuncAttributeMaxDynamicSharedMemorySize, SMEM_BYTES);
    cudaFuncSetAttribute(ns_mma<2>, cudaFuncAttributeMaxDynamicSharedMemorySize, SMEM_BYTES);

    rowsumq_kernel<<<dim3(CC, BB), 256>>>(x, s, q);
    trred_kernel<<<BB, 256>>>(s, q, tr);

    dim3 gg(3, 1, BB);
    gram_mma<<<gg, 512, SMEM_BYTES>>>(x, s, tr, A, B0);

    ns_mma<0><<<gg, 512, SMEM_BYTES>>>(A, B0, Y0, nullptr, nullptr);
    // iter 1
    ns_mma<1><<<gg, 512, SMEM_BYTES>>>(B0, Y0, B1, nullptr, nullptr);
    ns_mma<0><<<gg, 512, SMEM_BYTES>>>(Y0, B1, Y1, nullptr, nullptr);
    ns_mma<0><<<gg, 512, SMEM_BYTES>>>(B1, B0, Z0, nullptr, nullptr);
    // iter 2
    ns_mma<1><<<gg, 512, SMEM_BYTES>>>(Z0, Y1, B0, nullptr, nullptr);
    ns_mma<0><<<gg, 512, SMEM_BYTES>>>(Y1, B0, Y0, nullptr, nullptr);
    ns_mma<0><<<gg, 512, SMEM_BYTES>>>(B0, Z0, Z1, nullptr, nullptr);
    // iter 3
    ns_mma<1><<<gg, 512, SMEM_BYTES>>>(Z1, Y0, B1, nullptr, nullptr);
    ns_mma<0><<<gg, 512, SMEM_BYTES>>>(Y0, B1, Y1, nullptr, nullptr);
    ns_mma<0><<<gg, 512, SMEM_BYTES>>>(B1, Z1, Z0, nullptr, nullptr);
    // iter 4 (Z update dead -> dropped)
    ns_mma<1><<<gg, 512, SMEM_BYTES>>>(Z0, Y1, B0, nullptr, nullptr);
    ns_mma<2><<<gg, 512, SMEM_BYTES>>>(Y1, B0, nullptr, tr, out);
}